// round 1
// baseline (speedup 1.0000x reference)
#include <cuda_runtime.h>
#include <cuda_fp16.h>

#define N_NODES 100000
#define DIM     64
#define NB      8192
#define KP      32
#define KN      100

// Scratch (allocation-free rule: __device__ globals)
__device__ __half2 g_Z[N_NODES * (DIM / 2)];   // 12.8 MB, fp16 sigmoid(P)
__device__ float   g_acc[3];                   // [0]=sumsq deg, [1]=adj, [2]=deg_dist

// ---------------------------------------------------------------------------
__global__ void init_kernel() {
    if (threadIdx.x < 3) g_acc[threadIdx.x] = 0.0f;
}

// One warp per node row: sigmoid -> fp16 store, plus degree-loss partial.
__global__ void prep_kernel(const float* __restrict__ P,
                            const float* __restrict__ W,
                            const float* __restrict__ deg) {
    const int warp = (blockIdx.x * blockDim.x + threadIdx.x) >> 5;
    const int lane = threadIdx.x & 31;
    // grid sized exactly: 12500 blocks * 8 warps = 100000 rows
    const float2 p = *(const float2*)(P + (size_t)warp * DIM + lane * 2);
    const float z0 = 1.0f / (1.0f + __expf(-p.x));
    const float z1 = 1.0f / (1.0f + __expf(-p.y));
    g_Z[warp * 32 + lane] = __floats2half2_rn(z0, z1);

    const float2 w = *(const float2*)(W + lane * 2);
    float s = z0 * w.x + z1 * w.y;
    #pragma unroll
    for (int o = 16; o; o >>= 1) s += __shfl_xor_sync(0xFFFFFFFFu, s, o);

    __shared__ float sh[8];
    if (lane == 0) {
        const float dd = s - deg[warp];
        sh[threadIdx.x >> 5] = dd * dd;
    }
    __syncthreads();
    if (threadIdx.x == 0) {
        float t = 0.0f;
        #pragma unroll
        for (int i = 0; i < 8; i++) t += sh[i];
        atomicAdd(&g_acc[0], t);
    }
}

// ---------------------------------------------------------------------------
// |zi - z|_1 partial over the 8 dims this lane owns (16B of a 128B fp16 row).
__device__ __forceinline__ float ham8(uint4 raw, const float zi[8]) {
    const __half2* h = (const __half2*)&raw;
    float s = 0.0f;
    #pragma unroll
    for (int i = 0; i < 4; i++) {
        const float2 f = __half22float2(h[i]);
        s += fabsf(zi[2 * i] - f.x) + fabsf(zi[2 * i + 1] - f.y);
    }
    return s;
}

// One warp per selected node b. 8-lane groups each own one gathered row;
// a warp processes 4 neighbors per iteration.
__global__ void contrast_kernel(const int* __restrict__ sel,
                                const int* __restrict__ pos_adj,
                                const int* __restrict__ neg_adj,
                                const int* __restrict__ pos_deg,
                                const int* __restrict__ neg_deg) {
    const int warp = (blockIdx.x * blockDim.x + threadIdx.x) >> 5;
    const int lane = threadIdx.x & 31;
    if (warp >= NB) return;
    const int b  = warp;
    const int g  = lane >> 3;   // neighbor-group 0..3
    const int gl = lane & 7;    // lane within group: owns dims [gl*8, gl*8+8)

    // Zi for this lane's 8 dims (same for all 4 groups)
    float zi[8];
    {
        const int node = sel[b];
        const uint4 raw = *(const uint4*)(g_Z + node * 32 + gl * 4);
        const __half2* h = (const __half2*)&raw;
        #pragma unroll
        for (int i = 0; i < 4; i++) {
            const float2 f = __half22float2(h[i]);
            zi[2 * i] = f.x; zi[2 * i + 1] = f.y;
        }
    }

    float val[2];
    #pragma unroll
    for (int which = 0; which < 2; which++) {
        const int* plist = which ? pos_deg : pos_adj;
        const int* nlist = which ? neg_deg : neg_adj;

        // Positives: defer reduction, one butterfly at the end.
        float pos_sum = 0.0f;
        #pragma unroll
        for (int kb = 0; kb < KP; kb += 4) {
            const int idx = plist[b * KP + kb + g];
            const uint4 raw = *(const uint4*)(g_Z + idx * 32 + gl * 4);
            pos_sum += ham8(raw, zi);
        }
        #pragma unroll
        for (int o = 16; o; o >>= 1) pos_sum += __shfl_xor_sync(0xFFFFFFFFu, pos_sum, o);

        // Negatives: per-neighbor 8-lane reduce, then exp-accumulate.
        float negsum = 0.0f;
        #pragma unroll 5
        for (int kb = 0; kb < KN; kb += 4) {
            const int idx = nlist[b * KN + kb + g];
            const uint4 raw = *(const uint4*)(g_Z + idx * 32 + gl * 4);
            float s = ham8(raw, zi);
            s += __shfl_xor_sync(0xFFFFFFFFu, s, 1);
            s += __shfl_xor_sync(0xFFFFFFFFu, s, 2);
            s += __shfl_xor_sync(0xFFFFFFFFu, s, 4);
            negsum += __expf(s);
        }
        // sum across the 4 groups (values identical within a group)
        negsum += __shfl_xor_sync(0xFFFFFFFFu, negsum, 8);
        negsum += __shfl_xor_sync(0xFFFFFFFFu, negsum, 16);

        val[which] = -pos_sum * (1.0f / KP) + __logf(negsum);
    }

    __shared__ float sh1[8], sh2[8];
    if (lane == 0) {
        sh1[threadIdx.x >> 5] = val[0];
        sh2[threadIdx.x >> 5] = val[1];
    }
    __syncthreads();
    if (threadIdx.x == 0) {
        float t1 = 0.0f, t2 = 0.0f;
        #pragma unroll
        for (int i = 0; i < 8; i++) { t1 += sh1[i]; t2 += sh2[i]; }
        atomicAdd(&g_acc[1], t1);
        atomicAdd(&g_acc[2], t2);
    }
}

// ---------------------------------------------------------------------------
__global__ void finalize_kernel(float* __restrict__ out) {
    if (threadIdx.x == 0) {
        out[0] = sqrtf(g_acc[0]);
        out[1] = g_acc[1] * (1.0f / N_NODES);
        out[2] = g_acc[2] * (1.0f / N_NODES);
    }
}

// ---------------------------------------------------------------------------
extern "C" void kernel_launch(void* const* d_in, const int* in_sizes, int n_in,
                              void* d_out, int out_size) {
    const float* P   = (const float*)d_in[0];
    const float* W   = (const float*)d_in[1];
    const float* deg = (const float*)d_in[2];
    const int* sel   = (const int*)d_in[3];
    const int* pa    = (const int*)d_in[4];
    const int* na    = (const int*)d_in[5];
    const int* pd    = (const int*)d_in[6];
    const int* nd    = (const int*)d_in[7];
    float* out = (float*)d_out;

    init_kernel<<<1, 32>>>();
    prep_kernel<<<N_NODES / 8, 256>>>(P, W, deg);          // 12500 blocks, warp/row
    contrast_kernel<<<NB / 8, 256>>>(sel, pa, na, pd, nd); // 1024 blocks, warp/node
    finalize_kernel<<<1, 32>>>(out);
}

// round 2
// speedup vs baseline: 1.4518x; 1.4518x over previous
#include <cuda_runtime.h>
#include <cuda_fp16.h>

#define N_NODES 100000
#define DIM     64
#define NB      8192
#define KP      32
#define KN      100

// Scratch (allocation-free rule: __device__ globals; zero-initialized at load,
// and every kernel_launch execution leaves them zeroed again -> deterministic).
__device__ __half2  g_Z[N_NODES * (DIM / 2)];   // 12.8 MB, fp16 sigmoid(P)
__device__ float    g_acc[3];                   // [0]=sumsq deg, [1]=adj, [2]=deg_dist
__device__ unsigned g_count;                    // finalize election counter

// ---------------------------------------------------------------------------
// Prep: sigmoid(P) -> fp16 g_Z, plus degree-loss sum of squares.
// Grid-stride, one warp per row per iteration. 256 blocks x 1024 threads.
__global__ void prep_kernel(const float* __restrict__ P,
                            const float* __restrict__ W,
                            const float* __restrict__ deg) {
    const int lane   = threadIdx.x & 31;
    const int warp   = (blockIdx.x * blockDim.x + threadIdx.x) >> 5;
    const int nwarps = (gridDim.x * blockDim.x) >> 5;

    const float2 w = *(const float2*)(W + lane * 2);

    float acc = 0.0f;
    for (int row = warp; row < N_NODES; row += nwarps) {
        const float2 p = *(const float2*)(P + (size_t)row * DIM + lane * 2);
        const float z0 = 1.0f / (1.0f + __expf(-p.x));
        const float z1 = 1.0f / (1.0f + __expf(-p.y));
        g_Z[row * 32 + lane] = __floats2half2_rn(z0, z1);

        float s = z0 * w.x + z1 * w.y;
        #pragma unroll
        for (int o = 16; o; o >>= 1) s += __shfl_xor_sync(0xFFFFFFFFu, s, o);
        if (lane == 0) {
            const float dd = s - deg[row];
            acc += dd * dd;
        }
    }

    __shared__ float sh[32];
    if (lane == 0) sh[threadIdx.x >> 5] = acc;
    __syncthreads();
    if (threadIdx.x == 0) {
        float t = 0.0f;
        #pragma unroll
        for (int i = 0; i < 32; i++) t += sh[i];
        atomicAdd(&g_acc[0], t);
    }
}

// ---------------------------------------------------------------------------
// Half2 L1-distance partial over the 8 dims this lane owns (16B of a 128B row).
// 4x HSUB2 + (abs-folded) 3x HADD2 + 1 cvt + 1 FADD.
__device__ __forceinline__ float ham8h(uint4 raw, const __half2 zi[4]) {
    const __half2* h = (const __half2*)&raw;
    const __half2 d0 = __habs2(__hsub2(zi[0], h[0]));
    const __half2 d1 = __habs2(__hsub2(zi[1], h[1]));
    const __half2 d2 = __habs2(__hsub2(zi[2], h[2]));
    const __half2 d3 = __habs2(__hsub2(zi[3], h[3]));
    const __half2 t  = __hadd2(__hadd2(d0, d1), __hadd2(d2, d3));
    const float2  f  = __half22float2(t);
    return f.x + f.y;
}

// One warp per selected node b. 8-lane groups each own one gathered row;
// a warp processes 4 neighbor rows per iteration. Last block finalizes.
__global__ void contrast_kernel(const int* __restrict__ sel,
                                const int* __restrict__ pos_adj,
                                const int* __restrict__ neg_adj,
                                const int* __restrict__ pos_deg,
                                const int* __restrict__ neg_deg,
                                float* __restrict__ out) {
    const int warp = (blockIdx.x * blockDim.x + threadIdx.x) >> 5;
    const int lane = threadIdx.x & 31;
    const int b  = warp;                  // grid sized exactly: 1024*8 = NB warps
    const int g  = lane >> 3;             // neighbor-group 0..3
    const int gl = lane & 7;              // owns dims [gl*8, gl*8+8)

    // Zi for this lane's 8 dims (replicated across the 4 groups)
    __half2 zi[4];
    {
        const uint4 zr = *(const uint4*)(g_Z + sel[b] * 32 + gl * 4);
        const __half2* h = (const __half2*)&zr;
        zi[0] = h[0]; zi[1] = h[1]; zi[2] = h[2]; zi[3] = h[3];
    }

    float val[2];
    #pragma unroll
    for (int which = 0; which < 2; which++) {
        const int* plist = which ? pos_deg : pos_adj;
        const int* nlist = which ? neg_deg : neg_adj;

        // Positives: defer reduction to one butterfly at the end.
        float pos_sum = 0.0f;
        #pragma unroll
        for (int kb = 0; kb < KP; kb += 4) {
            const int idx = plist[b * KP + kb + g];
            pos_sum += ham8h(*(const uint4*)(g_Z + idx * 32 + gl * 4), zi);
        }
        #pragma unroll
        for (int o = 16; o; o >>= 1)
            pos_sum += __shfl_xor_sync(0xFFFFFFFFu, pos_sum, o);

        // Negatives: 8-lane reduce per row, then exp-accumulate per group.
        float negsum = 0.0f;
        #pragma unroll 5
        for (int kb = 0; kb < KN; kb += 4) {
            const int idx = nlist[b * KN + kb + g];
            float s = ham8h(*(const uint4*)(g_Z + idx * 32 + gl * 4), zi);
            s += __shfl_xor_sync(0xFFFFFFFFu, s, 1);
            s += __shfl_xor_sync(0xFFFFFFFFu, s, 2);
            s += __shfl_xor_sync(0xFFFFFFFFu, s, 4);
            negsum += __expf(s);
        }
        negsum += __shfl_xor_sync(0xFFFFFFFFu, negsum, 8);
        negsum += __shfl_xor_sync(0xFFFFFFFFu, negsum, 16);

        val[which] = -pos_sum * (1.0f / KP) + __logf(negsum);
    }

    __shared__ float sh1[8], sh2[8];
    __shared__ bool  sh_last;
    if (lane == 0) {
        sh1[threadIdx.x >> 5] = val[0];
        sh2[threadIdx.x >> 5] = val[1];
    }
    __syncthreads();
    if (threadIdx.x == 0) {
        float t1 = 0.0f, t2 = 0.0f;
        #pragma unroll
        for (int i = 0; i < 8; i++) { t1 += sh1[i]; t2 += sh2[i]; }
        atomicAdd(&g_acc[1], t1);
        atomicAdd(&g_acc[2], t2);
        __threadfence();
        sh_last = (atomicAdd(&g_count, 1u) == gridDim.x - 1);
    }
    __syncthreads();
    if (threadIdx.x == 0 && sh_last) {
        // All blocks' atomics are globally visible (fence + counter).
        const float a0 = *(volatile float*)&g_acc[0];
        const float a1 = *(volatile float*)&g_acc[1];
        const float a2 = *(volatile float*)&g_acc[2];
        out[0] = sqrtf(a0);
        out[1] = a1 * (1.0f / N_NODES);
        out[2] = a2 * (1.0f / N_NODES);
        // Reset scratch for the next (graph-replayed) execution.
        g_acc[0] = 0.0f; g_acc[1] = 0.0f; g_acc[2] = 0.0f;
        g_count = 0u;
    }
}

// ---------------------------------------------------------------------------
extern "C" void kernel_launch(void* const* d_in, const int* in_sizes, int n_in,
                              void* d_out, int out_size) {
    const float* P   = (const float*)d_in[0];
    const float* W   = (const float*)d_in[1];
    const float* deg = (const float*)d_in[2];
    const int* sel   = (const int*)d_in[3];
    const int* pa    = (const int*)d_in[4];
    const int* na    = (const int*)d_in[5];
    const int* pd    = (const int*)d_in[6];
    const int* nd    = (const int*)d_in[7];
    float* out = (float*)d_out;

    prep_kernel<<<256, 1024>>>(P, W, deg);
    contrast_kernel<<<NB / 8, 256>>>(sel, pa, na, pd, nd, out);
}

// round 5
// speedup vs baseline: 1.8390x; 1.2667x over previous
#include <cuda_runtime.h>
#include <cuda_fp16.h>

#define N_NODES 100000
#define DIM     64
#define NB      8192
#define KP      32
#define KN      100
#define INV255  (1.0f / 255.0f)

// Scratch (__device__ globals; left zeroed after every execution -> deterministic).
__device__ unsigned g_Zq[N_NODES * 16];   // 6.4 MB, u8-quantized sigmoid(P), 64B/row
__device__ float    g_acc[3];             // [0]=sumsq deg, [1]=adj, [2]=deg_dist
__device__ unsigned g_count;              // finalize election counter

// ---------------------------------------------------------------------------
// Prep: sigmoid(P) -> u8 g_Zq (x255), plus degree-loss sum of squares (fp32).
__global__ void prep_kernel(const float* __restrict__ P,
                            const float* __restrict__ W,
                            const float* __restrict__ deg) {
    const int lane   = threadIdx.x & 31;
    const int warp   = (blockIdx.x * blockDim.x + threadIdx.x) >> 5;
    const int nwarps = (gridDim.x * blockDim.x) >> 5;

    const float2 w = *(const float2*)(W + lane * 2);

    float acc = 0.0f;
    for (int row = warp; row < N_NODES; row += nwarps) {
        const float2 p = *(const float2*)(P + (size_t)row * DIM + lane * 2);
        const float z0 = 1.0f / (1.0f + __expf(-p.x));
        const float z1 = 1.0f / (1.0f + __expf(-p.y));

        // quantize to u8 (z in (0,1), so 0..255 after x255 round)
        const unsigned q0 = __float2uint_rn(z0 * 255.0f);
        const unsigned q1 = __float2uint_rn(z1 * 255.0f);
        ((unsigned short*)g_Zq)[row * 32 + lane] = (unsigned short)(q0 | (q1 << 8));

        float s = z0 * w.x + z1 * w.y;
        #pragma unroll
        for (int o = 16; o; o >>= 1) s += __shfl_xor_sync(0xFFFFFFFFu, s, o);
        if (lane == 0) {
            const float dd = s - deg[row];
            acc += dd * dd;
        }
    }

    __shared__ float sh[32];
    if (lane == 0) sh[threadIdx.x >> 5] = acc;
    __syncthreads();
    if (threadIdx.x == 0) {
        float t = 0.0f;
        #pragma unroll
        for (int i = 0; i < 32; i++) t += sh[i];
        atomicAdd(&g_acc[0], t);
    }
}

// ---------------------------------------------------------------------------
// SAD over this lane's 16 dims (16B of a 64B row): 4x VABSDIFF4 + 4x IDP4A.
__device__ __forceinline__ unsigned sad16(uint4 r, uint4 zi, unsigned acc) {
    acc = __dp4a(__vabsdiffu4(zi.x, r.x), 0x01010101u, acc);
    acc = __dp4a(__vabsdiffu4(zi.y, r.y), 0x01010101u, acc);
    acc = __dp4a(__vabsdiffu4(zi.z, r.z), 0x01010101u, acc);
    acc = __dp4a(__vabsdiffu4(zi.w, r.w), 0x01010101u, acc);
    return acc;
}

// One warp per selected node b. 4-lane groups each own one gathered 64B row;
// a warp processes 8 neighbor rows per iteration. Last block finalizes.
__global__ void contrast_kernel(const int* __restrict__ sel,
                                const int* __restrict__ pos_adj,
                                const int* __restrict__ neg_adj,
                                const int* __restrict__ pos_deg,
                                const int* __restrict__ neg_deg,
                                float* __restrict__ out) {
    const int warp = (blockIdx.x * blockDim.x + threadIdx.x) >> 5;
    const int lane = threadIdx.x & 31;
    const int b  = warp;                  // grid sized exactly: 1024*8 = NB warps
    const int g  = lane >> 2;             // neighbor-group 0..7
    const int gl = lane & 3;              // owns dims [gl*16, gl*16+16)

    const uint4 zi = *(const uint4*)(g_Zq + sel[b] * 16 + gl * 4);

    float val[2];
    #pragma unroll
    for (int which = 0; which < 2; which++) {
        const int* plist = which ? pos_deg : pos_adj;
        const int* nlist = which ? neg_deg : neg_adj;

        // Positives: pure int accumulation, one butterfly at the end.
        unsigned pos_acc = 0u;
        #pragma unroll
        for (int kb = 0; kb < KP; kb += 8) {
            const int idx = plist[b * KP + kb + g];
            pos_acc = sad16(*(const uint4*)(g_Zq + idx * 16 + gl * 4), zi, pos_acc);
        }
        #pragma unroll
        for (int o = 16; o; o >>= 1)
            pos_acc += __shfl_xor_sync(0xFFFFFFFFu, pos_acc, o);

        // Negatives: 12 full iterations of 8 rows + tail of 4 rows.
        float negsum = 0.0f;
        #pragma unroll 4
        for (int kb = 0; kb < 96; kb += 8) {
            const int idx = nlist[b * KN + kb + g];
            unsigned s = sad16(*(const uint4*)(g_Zq + idx * 16 + gl * 4), zi, 0u);
            s += __shfl_xor_sync(0xFFFFFFFFu, s, 1);
            s += __shfl_xor_sync(0xFFFFFFFFu, s, 2);
            negsum += __expf(__uint2float_rn(s) * INV255);
        }
        {   // tail: rows 96..99 handled by groups 0..3
            const int idx = nlist[b * KN + 96 + (g & 3)];
            unsigned s = sad16(*(const uint4*)(g_Zq + idx * 16 + gl * 4), zi, 0u);
            s += __shfl_xor_sync(0xFFFFFFFFu, s, 1);
            s += __shfl_xor_sync(0xFFFFFFFFu, s, 2);
            if (g < 4) negsum += __expf(__uint2float_rn(s) * INV255);
        }
        negsum += __shfl_xor_sync(0xFFFFFFFFu, negsum, 4);
        negsum += __shfl_xor_sync(0xFFFFFFFFu, negsum, 8);
        negsum += __shfl_xor_sync(0xFFFFFFFFu, negsum, 16);

        val[which] = -__uint2float_rn(pos_acc) * (INV255 / KP) + __logf(negsum);
    }

    __shared__ float sh1[8], sh2[8];
    __shared__ bool  sh_last;
    if (lane == 0) {
        sh1[threadIdx.x >> 5] = val[0];
        sh2[threadIdx.x >> 5] = val[1];
    }
    __syncthreads();
    if (threadIdx.x == 0) {
        float t1 = 0.0f, t2 = 0.0f;
        #pragma unroll
        for (int i = 0; i < 8; i++) { t1 += sh1[i]; t2 += sh2[i]; }
        atomicAdd(&g_acc[1], t1);
        atomicAdd(&g_acc[2], t2);
        __threadfence();
        sh_last = (atomicAdd(&g_count, 1u) == gridDim.x - 1);
    }
    __syncthreads();
    if (threadIdx.x == 0 && sh_last) {
        const float a0 = *(volatile float*)&g_acc[0];
        const float a1 = *(volatile float*)&g_acc[1];
        const float a2 = *(volatile float*)&g_acc[2];
        out[0] = sqrtf(a0);
        out[1] = a1 * (1.0f / N_NODES);
        out[2] = a2 * (1.0f / N_NODES);
        g_acc[0] = 0.0f; g_acc[1] = 0.0f; g_acc[2] = 0.0f;
        g_count = 0u;
    }
}

// ---------------------------------------------------------------------------
extern "C" void kernel_launch(void* const* d_in, const int* in_sizes, int n_in,
                              void* d_out, int out_size) {
    const float* P   = (const float*)d_in[0];
    const float* W   = (const float*)d_in[1];
    const float* deg = (const float*)d_in[2];
    const int* sel   = (const int*)d_in[3];
    const int* pa    = (const int*)d_in[4];
    const int* na    = (const int*)d_in[5];
    const int* pd    = (const int*)d_in[6];
    const int* nd    = (const int*)d_in[7];
    float* out = (float*)d_out;

    prep_kernel<<<256, 1024>>>(P, W, deg);
    contrast_kernel<<<NB / 8, 256>>>(sel, pa, na, pd, nd, out);
}

// round 7
// speedup vs baseline: 1.8638x; 1.0135x over previous
#include <cuda_runtime.h>
#include <cuda_fp16.h>

#define N_NODES 100000
#define DIM     64
#define NB      8192
#define KP      32
#define KN      100
#define INV255  (1.0f / 255.0f)
#define B_PER_BLK 8

// Scratch (__device__ globals; left zeroed after every execution -> deterministic).
__device__ unsigned g_Zq[N_NODES * 16];   // 6.4 MB, u8-quantized sigmoid(P), 64B/row
__device__ float    g_acc[3];             // [0]=sumsq deg, [1]=adj, [2]=deg_dist
__device__ unsigned g_count;              // finalize election counter

// ---------------------------------------------------------------------------
// Prep: sigmoid(P) -> u8 g_Zq (x255), plus degree-loss sum of squares (fp32).
__global__ void prep_kernel(const float* __restrict__ P,
                            const float* __restrict__ W,
                            const float* __restrict__ deg) {
    const int lane   = threadIdx.x & 31;
    const int warp   = (blockIdx.x * blockDim.x + threadIdx.x) >> 5;
    const int nwarps = (gridDim.x * blockDim.x) >> 5;

    const float2 w = *(const float2*)(W + lane * 2);

    float acc = 0.0f;
    for (int row = warp; row < N_NODES; row += nwarps) {
        const float2 p = *(const float2*)(P + (size_t)row * DIM + lane * 2);
        const float z0 = 1.0f / (1.0f + __expf(-p.x));
        const float z1 = 1.0f / (1.0f + __expf(-p.y));

        const unsigned q0 = __float2uint_rn(z0 * 255.0f);
        const unsigned q1 = __float2uint_rn(z1 * 255.0f);
        ((unsigned short*)g_Zq)[row * 32 + lane] = (unsigned short)(q0 | (q1 << 8));

        float s = z0 * w.x + z1 * w.y;
        #pragma unroll
        for (int o = 16; o; o >>= 1) s += __shfl_xor_sync(0xFFFFFFFFu, s, o);
        if (lane == 0) {
            const float dd = s - deg[row];
            acc += dd * dd;
        }
    }

    __shared__ float sh[32];
    if (lane == 0) sh[threadIdx.x >> 5] = acc;
    __syncthreads();
    if (threadIdx.x == 0) {
        float t = 0.0f;
        #pragma unroll
        for (int i = 0; i < 32; i++) t += sh[i];
        atomicAdd(&g_acc[0], t);
    }
}

// ---------------------------------------------------------------------------
// SAD over this lane's 16 dims (16B of a 64B row): 4x VABSDIFF4 + 4x IDP4A.
__device__ __forceinline__ unsigned sad16(uint4 r, uint4 zi, unsigned acc) {
    acc = __dp4a(__vabsdiffu4(zi.x, r.x), 0x01010101u, acc);
    acc = __dp4a(__vabsdiffu4(zi.y, r.y), 0x01010101u, acc);
    acc = __dp4a(__vabsdiffu4(zi.z, r.z), 0x01010101u, acc);
    acc = __dp4a(__vabsdiffu4(zi.w, r.w), 0x01010101u, acc);
    return acc;
}

// One warp per selected node b; 8 b's per block. All indices staged in SMEM
// up front (coalesced) so the hot loop's only global loads are row gathers.
// 4-lane groups each own one gathered 64B row; 8 rows per warp iteration.
__global__ __launch_bounds__(256) void contrast_kernel(
        const int* __restrict__ sel,
        const int* __restrict__ pos_adj,
        const int* __restrict__ neg_adj,
        const int* __restrict__ pos_deg,
        const int* __restrict__ neg_deg,
        float* __restrict__ out) {
    __shared__ int s_pos[2][B_PER_BLK][KP];   // 2 KB
    __shared__ int s_neg[2][B_PER_BLK][KN];   // 6.4 KB
    __shared__ int s_sel[B_PER_BLK];

    const int tid  = threadIdx.x;
    const int warp = tid >> 5;
    const int lane = tid & 31;
    const int b_base = blockIdx.x * B_PER_BLK;

    // ---- stage all indices for this block (fully coalesced) ----
    ((int*)s_pos[0])[tid] = pos_adj[b_base * KP + tid];      // 256 ints exactly
    ((int*)s_pos[1])[tid] = pos_deg[b_base * KP + tid];
    #pragma unroll
    for (int i = 0; i < 4; i++) {                            // 800 <= 4*256
        const int j = tid + i * 256;
        if (j < B_PER_BLK * KN) {
            ((int*)s_neg[0])[j] = neg_adj[b_base * KN + j];
            ((int*)s_neg[1])[j] = neg_deg[b_base * KN + j];
        }
    }
    if (tid < B_PER_BLK) s_sel[tid] = sel[b_base + tid];
    __syncthreads();

    const int g  = lane >> 2;             // neighbor-group 0..7
    const int gl = lane & 3;              // owns dims [gl*16, gl*16+16)

    const uint4 zi = *(const uint4*)(g_Zq + s_sel[warp] * 16 + gl * 4);

    float val[2];
    #pragma unroll
    for (int which = 0; which < 2; which++) {
        // Positives: pure int accumulation, one butterfly at the end.
        unsigned pos_acc = 0u;
        #pragma unroll
        for (int kb = 0; kb < KP; kb += 8) {
            const int idx = s_pos[which][warp][kb + g];
            pos_acc = sad16(*(const uint4*)(g_Zq + idx * 16 + gl * 4), zi, pos_acc);
        }
        #pragma unroll
        for (int o = 16; o; o >>= 1)
            pos_acc += __shfl_xor_sync(0xFFFFFFFFu, pos_acc, o);

        // Negatives: 12 full iterations of 8 rows + tail of 4 rows.
        float negsum = 0.0f;
        #pragma unroll 4
        for (int kb = 0; kb < 96; kb += 8) {
            const int idx = s_neg[which][warp][kb + g];
            unsigned s = sad16(*(const uint4*)(g_Zq + idx * 16 + gl * 4), zi, 0u);
            s += __shfl_xor_sync(0xFFFFFFFFu, s, 1);
            s += __shfl_xor_sync(0xFFFFFFFFu, s, 2);
            negsum += __expf(__uint2float_rn(s) * INV255);
        }
        {   // tail: rows 96..99 handled by groups 0..3
            const int idx = s_neg[which][warp][96 + (g & 3)];
            unsigned s = sad16(*(const uint4*)(g_Zq + idx * 16 + gl * 4), zi, 0u);
            s += __shfl_xor_sync(0xFFFFFFFFu, s, 1);
            s += __shfl_xor_sync(0xFFFFFFFFu, s, 2);
            if (g < 4) negsum += __expf(__uint2float_rn(s) * INV255);
        }
        negsum += __shfl_xor_sync(0xFFFFFFFFu, negsum, 4);
        negsum += __shfl_xor_sync(0xFFFFFFFFu, negsum, 8);
        negsum += __shfl_xor_sync(0xFFFFFFFFu, negsum, 16);

        val[which] = -__uint2float_rn(pos_acc) * (INV255 / KP) + __logf(negsum);
    }

    __shared__ float sh1[8], sh2[8];
    __shared__ bool  sh_last;
    if (lane == 0) {
        sh1[warp] = val[0];
        sh2[warp] = val[1];
    }
    __syncthreads();
    if (tid == 0) {
        float t1 = 0.0f, t2 = 0.0f;
        #pragma unroll
        for (int i = 0; i < 8; i++) { t1 += sh1[i]; t2 += sh2[i]; }
        atomicAdd(&g_acc[1], t1);
        atomicAdd(&g_acc[2], t2);
        __threadfence();
        sh_last = (atomicAdd(&g_count, 1u) == gridDim.x - 1);
    }
    __syncthreads();
    if (tid == 0 && sh_last) {
        const float a0 = *(volatile float*)&g_acc[0];
        const float a1 = *(volatile float*)&g_acc[1];
        const float a2 = *(volatile float*)&g_acc[2];
        out[0] = sqrtf(a0);
        out[1] = a1 * (1.0f / N_NODES);
        out[2] = a2 * (1.0f / N_NODES);
        g_acc[0] = 0.0f; g_acc[1] = 0.0f; g_acc[2] = 0.0f;
        g_count = 0u;
    }
}

// ---------------------------------------------------------------------------
extern "C" void kernel_launch(void* const* d_in, const int* in_sizes, int n_in,
                              void* d_out, int out_size) {
    const float* P   = (const float*)d_in[0];
    const float* W   = (const float*)d_in[1];
    const float* deg = (const float*)d_in[2];
    const int* sel   = (const int*)d_in[3];
    const int* pa    = (const int*)d_in[4];
    const int* na    = (const int*)d_in[5];
    const int* pd    = (const int*)d_in[6];
    const int* nd    = (const int*)d_in[7];
    float* out = (float*)d_out;

    prep_kernel<<<256, 1024>>>(P, W, deg);
    contrast_kernel<<<NB / B_PER_BLK, 256>>>(sel, pa, na, pd, nd, out);
}